// round 10
// baseline (speedup 1.0000x reference)
#include <cuda_runtime.h>
#include <cuda_bf16.h>
#include <cstdint>

#define NN 100000
#define EE 1600000
#define NT64 ((NN + 63) / 64)    // 1563 tiles of 64 rows

typedef uint32_t u32;

// ---------------- scratch (static device globals; no allocations) ----------
__device__ __nv_bfloat16  g_hhi[(NN + 128) * 64];  // node features, bf16 hi part
__device__ __nv_bfloat16  g_hlo[(NN + 128) * 64];  // node features, bf16 lo part
__device__ float          g_pq[NN * 128];  // p (cols 0-63), q (cols 64-127)
__device__ int            g_src[EE];       // int32 source indices
__device__ unsigned       g_gmax[64];      // global max bits (values >= 0)
__device__ float          g_c128[128];     // head constant: g @ Wa[64:128] + ba
__device__ __nv_bfloat16  g_whi[5 * 128 * 64];  // weight hi parts, [n][k] flat
__device__ __nv_bfloat16  g_wlo[5 * 128 * 64];  // weight lo parts

// ---------------- convert (fused gmax zero + dtype detect) ------------------
__global__ void convert_kernel(const int* __restrict__ ei) {
    __shared__ int s64;
    if (blockIdx.x == 0 && threadIdx.x < 64) g_gmax[threadIdx.x] = 0u;
    if (threadIdx.x == 0) {
        // int64 layout => odd words of src row all zero (0<=src<1e5);
        // int32 layout => P(all 64 zero) ~ 1e-320.
        int z = 0;
        for (int i = 0; i < 64; i++) z += (ei[2 * i + 1] == 0) ? 1 : 0;
        s64 = (z == 64) ? 1 : 0;
    }
    __syncthreads();
    int e = blockIdx.x * blockDim.x + threadIdx.x;
    if (e < EE) g_src[e] = s64 ? ei[2 * e] : ei[e];
}

// ---------------- layer 1: warp-per-node + fused weight prep ---------------
__global__ void layer1_kernel(const float* __restrict__ x,
                              const float* __restrict__ W1,
                              const float* __restrict__ b1,
                              const float* __restrict__ Wl0,
                              const float* __restrict__ Wl1,
                              const float* __restrict__ Wl2,
                              const float* __restrict__ Wl3,
                              const float* __restrict__ Wa) {
    if (blockIdx.x >= 12500) {
        int b = blockIdx.x - 12500;
        const float* W = (b == 0) ? Wl0 : (b == 1) ? Wl1 : (b == 2) ? Wl2
                       : (b == 3) ? Wl3 : Wa;
        for (int i = threadIdx.x; i < 8192; i += 256) {
            int n = i >> 6, k = i & 63;
            float wv;
            if (b < 4)
                wv = (n < 64) ? (W[k * 64 + n] - W[(k + 64) * 64 + n])
                              : W[(k + 64) * 64 + (n - 64)];
            else
                wv = W[k * 128 + n];
            __nv_bfloat16 hi = __float2bfloat16(wv);
            __nv_bfloat16 lo = __float2bfloat16(wv - __bfloat162float(hi));
            g_whi[b * 8192 + i] = hi;
            g_wlo[b * 8192 + i] = lo;
        }
        return;
    }
    __shared__ float sW[384];   // W1: 6 rows x 64
    __shared__ float sb[64];
    int tid = threadIdx.x;
    for (int i = tid; i < 448; i += 256) {
        if (i < 384) sW[i] = W1[i];
        else         sb[i - 384] = b1[i - 384];
    }
    __syncthreads();
    int lane = tid & 31;
    int node = blockIdx.x * 8 + (tid >> 5);
    float xv = (lane < 3) ? x[node * 3 + lane] : 0.f;
    float x0 = __shfl_sync(0xffffffffu, xv, 0);
    float x1 = __shfl_sync(0xffffffffu, xv, 1);
    float x2 = __shfl_sync(0xffffffffu, xv, 2);
    int c = lane * 2;
    float w30 = sW[192 + c], w31 = sW[193 + c];
    float w40 = sW[256 + c], w41 = sW[257 + c];
    float w50 = sW[320 + c], w51 = sW[321 + c];
    float q0 = x0 * w30 + x1 * w40 + x2 * w50;
    float q1 = x0 * w31 + x1 * w41 + x2 * w51;
    float p0 = sb[c]     + x0 * (sW[c] - w30)     + x1 * (sW[64 + c] - w40)
                         + x2 * (sW[128 + c] - w50);
    float p1 = sb[c + 1] + x0 * (sW[c + 1] - w31) + x1 * (sW[65 + c] - w41)
                         + x2 * (sW[129 + c] - w51);
    *(float2*)(g_pq + node * 128 + c)      = make_float2(p0, p1);
    *(float2*)(g_pq + node * 128 + 64 + c) = make_float2(q0, q1);
}

// ---------------- edge max: 2 nodes per warp, float4 lanes ------------------
__global__ void edge_kernel(int dogmax) {
    __shared__ unsigned sm[64];
    int gw   = (blockIdx.x * blockDim.x + threadIdx.x) >> 5;  // warp: 2 nodes
    int lane = threadIdx.x & 31;
    int half = lane >> 4;
    int hl   = lane & 15;
    int node = gw * 2 + half;
    int s = g_src[gw * 32 + lane];   // lanes 0-15: node0 srcs, 16-31: node1
    float4 m = make_float4(-3.402823466e38f, -3.402823466e38f,
                           -3.402823466e38f, -3.402823466e38f);
    const float* pq = g_pq;
#pragma unroll
    for (int k = 0; k < 16; k++) {
        int j = __shfl_sync(0xffffffffu, s, (half << 4) + k);
        float4 v = *(const float4*)(pq + j * 128 + 64 + hl * 4);
        m.x = fmaxf(m.x, v.x);
        m.y = fmaxf(m.y, v.y);
        m.z = fmaxf(m.z, v.z);
        m.w = fmaxf(m.w, v.w);
    }
    float4 p = *(const float4*)(pq + node * 128 + hl * 4);
    float r0 = fmaxf(p.x + m.x, 0.f);
    float r1 = fmaxf(p.y + m.y, 0.f);
    float r2 = fmaxf(p.z + m.z, 0.f);
    float r3 = fmaxf(p.w + m.w, 0.f);
    __nv_bfloat16 h0 = __float2bfloat16(r0), h1 = __float2bfloat16(r1);
    __nv_bfloat16 h2 = __float2bfloat16(r2), h3 = __float2bfloat16(r3);
    __nv_bfloat16 l0 = __float2bfloat16(r0 - __bfloat162float(h0));
    __nv_bfloat16 l1 = __float2bfloat16(r1 - __bfloat162float(h1));
    __nv_bfloat16 l2 = __float2bfloat16(r2 - __bfloat162float(h2));
    __nv_bfloat16 l3 = __float2bfloat16(r3 - __bfloat162float(h3));
    __nv_bfloat162 hp0 = __halves2bfloat162(h0, h1);
    __nv_bfloat162 hp1 = __halves2bfloat162(h2, h3);
    __nv_bfloat162 lp0 = __halves2bfloat162(l0, l1);
    __nv_bfloat162 lp1 = __halves2bfloat162(l2, l3);
    uint2 hv = make_uint2(*(u32*)&hp0, *(u32*)&hp1);
    uint2 lv = make_uint2(*(u32*)&lp0, *(u32*)&lp1);
    *(uint2*)(g_hhi + node * 64 + hl * 4) = hv;
    *(uint2*)(g_hlo + node * 64 + hl * 4) = lv;
    if (dogmax) {
        if (threadIdx.x < 64) sm[threadIdx.x] = 0u;
        __syncthreads();
        atomicMax(&sm[hl * 4 + 0], __float_as_uint(r0));   // r >= 0
        atomicMax(&sm[hl * 4 + 1], __float_as_uint(r1));
        atomicMax(&sm[hl * 4 + 2], __float_as_uint(r2));
        atomicMax(&sm[hl * 4 + 3], __float_as_uint(r3));
        __syncthreads();
        if (threadIdx.x < 64) atomicMax(&g_gmax[threadIdx.x], sm[threadIdx.x]);
    }
}

// ---------------- mma / ldmatrix / cp.async helpers -------------------------
static __device__ __forceinline__ void mma16816(float d[4], const u32 a[4],
                                                const u32 b[2]) {
    asm volatile(
        "mma.sync.aligned.m16n8k16.row.col.f32.bf16.bf16.f32 "
        "{%0,%1,%2,%3}, {%4,%5,%6,%7}, {%8,%9}, {%0,%1,%2,%3};"
        : "+f"(d[0]), "+f"(d[1]), "+f"(d[2]), "+f"(d[3])
        : "r"(a[0]), "r"(a[1]), "r"(a[2]), "r"(a[3]), "r"(b[0]), "r"(b[1]));
}
static __device__ __forceinline__ void ldsm4(u32 r[4], u32 addr) {
    asm volatile("ldmatrix.sync.aligned.m8n8.x4.shared.b16 {%0,%1,%2,%3}, [%4];"
        : "=r"(r[0]), "=r"(r[1]), "=r"(r[2]), "=r"(r[3]) : "r"(addr));
}
static __device__ __forceinline__ u32 smem_u32(const void* p) {
    u32 a;
    asm("{ .reg .u64 t; cvta.to.shared.u64 t, %1; cvt.u32.u64 %0, t; }"
        : "=r"(a) : "l"(p));
    return a;
}
static __device__ __forceinline__ void cpasync16(u32 dst, const void* src) {
    asm volatile("cp.async.cg.shared.global [%0], [%1], 16;"
        :: "r"(dst), "l"(src) : "memory");
}
static __device__ __forceinline__ void cpasync_wait_all() {
    asm volatile("cp.async.commit_group;\n\tcp.async.wait_group 0;" ::: "memory");
}

// ---------------- tensor-core GEMM: h[N,64] @ Wc[64,128] -> g_pq ------------
// Occupancy-first tiling: CTA = 64M x 128N, 256 thr (8 warps), 4 CTAs/SM
// (smem 55.8KB, <=64 regs). Warp tile 32M x 32N with M-OUTER loop (mt=0,1):
// only 16 accumulators + 16 frag regs live. 3-pass bf16 hi/lo split
// (Ahi*Bhi + Alo*Bhi + Ahi*Blo), fp32 accum. Rows padded to 72 bf16 (144B).
// smem: Bhi[128][72] @0, Blo @18432, Ahi[64][72] @36864, Alo @46080,
//       bias @55296. Total 55808 B.
// mode 0: bias on cols 0-63.  mode 1: bias g_c128, relu at store.
__global__ void __launch_bounds__(256, 4) tc_gemm_kernel(int layer,
                                                         const float* __restrict__ bias,
                                                         int mode) {
    extern __shared__ unsigned char smem[];
    float* sB = (float*)(smem + 55296);
    int tid = threadIdx.x;
    int nb  = blockIdx.x * 64;
    u32 sbase = smem_u32(smem);

    // B: 128 rows x 8 chunks x {hi,lo} = 2048 chunks
    {
        const char* wh = (const char*)(g_whi + layer * 8192);
        const char* wl = (const char*)(g_wlo + layer * 8192);
#pragma unroll
        for (int c = tid; c < 2048; c += 256) {
            int half = c >> 10, idx = c & 1023;
            u32 off = (u32)(idx >> 3) * 144 + (u32)(idx & 7) * 16;
            cpasync16(sbase + half * 18432 + off,
                      (half ? wl : wh) + idx * 16);
        }
    }
    // A: 64 rows x 8 chunks x {hi,lo} = 1024 chunks (gmem oversized past NN)
    {
        const char* ah = (const char*)(g_hhi + (size_t)nb * 64);
        const char* al = (const char*)(g_hlo + (size_t)nb * 64);
#pragma unroll
        for (int c = tid; c < 1024; c += 256) {
            int half = c >> 9, idx = c & 511;
            u32 off = (u32)(idx >> 3) * 144 + (u32)(idx & 7) * 16;
            cpasync16(sbase + 36864 + half * 9216 + off,
                      (half ? al : ah) + idx * 16);
        }
    }
    if (tid < 128)
        sB[tid] = (mode == 0) ? ((tid < 64) ? bias[tid] : 0.f) : g_c128[tid];
    cpasync_wait_all();
    __syncthreads();

    int lane = tid & 31;
    int wid  = tid >> 5;
    int wm   = wid & 1;      // 32-row group
    int wn   = wid >> 1;     // 32-col group

    int brow = wn * 32 + (lane & 7) + ((lane >> 4) << 3);
    u32 bHi = sbase + (brow * 72 + ((lane >> 3) & 1) * 8) * 2;
    u32 bLo = bHi + 18432;
    int r = lane >> 2, q = lane & 3;

#pragma unroll
    for (int mt = 0; mt < 2; mt++) {
        u32 aHi = sbase + 36864 +
                  ((wm * 32 + mt * 16 + (lane & 15)) * 72 + (lane >> 4) * 8) * 2;
        u32 aLo = aHi + 9216;

        float d[4][4];
#pragma unroll
        for (int nf = 0; nf < 4; nf++)
#pragma unroll
            for (int j = 0; j < 4; j++) d[nf][j] = 0.f;

#pragma unroll
        for (int kk = 0; kk < 4; kk++) {
            int ko = kk * 32;
            u32 ah[4], al[4], bb[2][4];
            ldsm4(ah, aHi + ko);
            ldsm4(al, aLo + ko);
            ldsm4(bb[0], bHi + ko);
            ldsm4(bb[1], bHi + 2304 + ko);
#pragma unroll
            for (int nf = 0; nf < 4; nf++) {
                mma16816(d[nf], ah, &bb[nf >> 1][(nf & 1) * 2]);
                mma16816(d[nf], al, &bb[nf >> 1][(nf & 1) * 2]);
            }
            ldsm4(bb[0], bLo + ko);
            ldsm4(bb[1], bLo + 2304 + ko);
#pragma unroll
            for (int nf = 0; nf < 4; nf++)
                mma16816(d[nf], ah, &bb[nf >> 1][(nf & 1) * 2]);
        }

        // epilogue for this mt
        int row0 = nb + wm * 32 + mt * 16 + r;
#pragma unroll
        for (int nf = 0; nf < 4; nf++) {
            int gcol = wn * 32 + nf * 8 + 2 * q;
            float bx = sB[gcol], by = sB[gcol + 1];
            float2 v0 = make_float2(d[nf][0] + bx, d[nf][1] + by);
            float2 v1 = make_float2(d[nf][2] + bx, d[nf][3] + by);
            if (mode == 1) {
                v0.x = fmaxf(v0.x, 0.f); v0.y = fmaxf(v0.y, 0.f);
                v1.x = fmaxf(v1.x, 0.f); v1.y = fmaxf(v1.y, 0.f);
            }
            if (row0 < NN)     *(float2*)(g_pq + row0 * 128 + gcol)       = v0;
            if (row0 + 8 < NN) *(float2*)(g_pq + (row0 + 8) * 128 + gcol) = v1;
        }
    }
}

// ---------------- c128 = ba + g @ Wa[64:128] --------------------------------
__global__ void c128_kernel(const float* __restrict__ Wa,
                            const float* __restrict__ ba) {
    int t = threadIdx.x;  // 128 threads
    float s = ba[t];
#pragma unroll 8
    for (int c = 0; c < 64; c++)
        s += __uint_as_float(g_gmax[c]) * Wa[(64 + c) * 128 + t];
    g_c128[t] = s;
}

// ---------------- head stage 2: out = x + r @ Wb + bb ----------------------
// ONE NODE PER WARP -> grid must cover NN warps = (NN*32)/256 blocks.
__global__ void head2_kernel(const float* __restrict__ Wb,
                             const float* __restrict__ bb,
                             const float* __restrict__ x,
                             float* __restrict__ out) {
    __shared__ float sWb[384];
    for (int i = threadIdx.x; i < 384; i += 256) sWb[i] = Wb[i];
    __syncthreads();
    int w    = (blockIdx.x * blockDim.x + threadIdx.x) >> 5;
    int lane = threadIdx.x & 31;
    if (w >= NN) return;
    float4 r4 = ((const float4*)(g_pq + w * 128))[lane];
    int t = lane * 4;
    float a0 = r4.x * sWb[t * 3 + 0] + r4.y * sWb[t * 3 + 3] +
               r4.z * sWb[t * 3 + 6] + r4.w * sWb[t * 3 + 9];
    float a1 = r4.x * sWb[t * 3 + 1] + r4.y * sWb[t * 3 + 4] +
               r4.z * sWb[t * 3 + 7] + r4.w * sWb[t * 3 + 10];
    float a2 = r4.x * sWb[t * 3 + 2] + r4.y * sWb[t * 3 + 5] +
               r4.z * sWb[t * 3 + 8] + r4.w * sWb[t * 3 + 11];
#pragma unroll
    for (int off = 16; off > 0; off >>= 1) {
        a0 += __shfl_down_sync(0xffffffffu, a0, off);
        a1 += __shfl_down_sync(0xffffffffu, a1, off);
        a2 += __shfl_down_sync(0xffffffffu, a2, off);
    }
    if (lane == 0) {
        out[w * 3 + 0] = x[w * 3 + 0] + bb[0] + a0;
        out[w * 3 + 1] = x[w * 3 + 1] + bb[1] + a1;
        out[w * 3 + 2] = x[w * 3 + 2] + bb[2] + a2;
    }
}

// ---------------- launch ----------------------------------------------------
extern "C" void kernel_launch(void* const* d_in, const int* in_sizes, int n_in,
                              void* d_out, int out_size) {
    (void)in_sizes; (void)n_in; (void)out_size;
    const float* x  = (const float*)d_in[0];
    const int*   ei = (const int*)d_in[1];
    const float* W1 = (const float*)d_in[2];
    const float* b1 = (const float*)d_in[3];
    const float* Wl[4] = {(const float*)d_in[4], (const float*)d_in[6],
                          (const float*)d_in[8], (const float*)d_in[10]};
    const float* bl[4] = {(const float*)d_in[5], (const float*)d_in[7],
                          (const float*)d_in[9], (const float*)d_in[11]};
    const float* Wa = (const float*)d_in[12];
    const float* ba = (const float*)d_in[13];
    const float* Wb = (const float*)d_in[14];
    const float* bb = (const float*)d_in[15];
    float* out = (float*)d_out;

    const int GEMM_SMEM = 55808;
    static bool attr_set = false;
    if (!attr_set) {
        cudaFuncSetAttribute(tc_gemm_kernel,
                             cudaFuncAttributeMaxDynamicSharedMemorySize,
                             GEMM_SMEM);
        attr_set = true;
    }

    convert_kernel<<<(EE + 255) / 256, 256>>>(ei);                        // #1
    layer1_kernel<<<12505, 256>>>(x, W1, b1, Wl[0], Wl[1], Wl[2], Wl[3], Wa); // #2
    edge_kernel<<<(NN * 16) / 256, 256>>>(0);                             // #3

    for (int l = 0; l < 4; l++) {
        tc_gemm_kernel<<<NT64, 256, GEMM_SMEM>>>(l, bl[l], 0);            // #4 (l=0)
        edge_kernel<<<(NN * 16) / 256, 256>>>(l == 3 ? 1 : 0);
    }

    c128_kernel<<<1, 128>>>(Wa, ba);
    tc_gemm_kernel<<<NT64, 256, GEMM_SMEM>>>(4, ba, 1);
    head2_kernel<<<(NN * 32) / 256, 256>>>(Wb, bb, x, out);   // 1 node/warp
}

// round 11
// speedup vs baseline: 1.0520x; 1.0520x over previous
#include <cuda_runtime.h>
#include <cuda_bf16.h>
#include <cstdint>

#define NN 100000
#define EE 1600000
#define NT128 ((NN + 127) / 128)   // 782 tiles of 128 rows

typedef uint32_t u32;

// ---------------- scratch (static device globals; no allocations) ----------
__device__ __nv_bfloat16  g_hhi[(NN + 128) * 64];  // node features, bf16 hi part
__device__ __nv_bfloat16  g_hlo[(NN + 128) * 64];  // node features, bf16 lo part
__device__ float          g_pq[NN * 128];  // p (cols 0-63), q (cols 64-127)
__device__ int            g_src[EE];       // int32 source indices
__device__ unsigned       g_gmax[64];      // global max bits (values >= 0)
__device__ float          g_c128[128];     // head constant: g @ Wa[64:128] + ba
__device__ __nv_bfloat16  g_whi[5 * 128 * 64];  // weight hi parts, [n][k] flat
__device__ __nv_bfloat16  g_wlo[5 * 128 * 64];  // weight lo parts

// ---------------- convert (fused gmax zero + dtype detect) ------------------
__global__ void convert_kernel(const int* __restrict__ ei) {
    __shared__ int s64;
    if (blockIdx.x == 0 && threadIdx.x < 64) g_gmax[threadIdx.x] = 0u;
    if (threadIdx.x == 0) {
        // int64 layout => odd words of src row all zero (0<=src<1e5);
        // int32 layout => P(all 64 zero) ~ 1e-320.
        int z = 0;
        for (int i = 0; i < 64; i++) z += (ei[2 * i + 1] == 0) ? 1 : 0;
        s64 = (z == 64) ? 1 : 0;
    }
    __syncthreads();
    int e = blockIdx.x * blockDim.x + threadIdx.x;
    if (e < EE) g_src[e] = s64 ? ei[2 * e] : ei[e];
}

// ---------------- layer 1: warp-per-node + fused weight prep ---------------
__global__ void layer1_kernel(const float* __restrict__ x,
                              const float* __restrict__ W1,
                              const float* __restrict__ b1,
                              const float* __restrict__ Wl0,
                              const float* __restrict__ Wl1,
                              const float* __restrict__ Wl2,
                              const float* __restrict__ Wl3,
                              const float* __restrict__ Wa) {
    if (blockIdx.x >= 12500) {
        int b = blockIdx.x - 12500;
        const float* W = (b == 0) ? Wl0 : (b == 1) ? Wl1 : (b == 2) ? Wl2
                       : (b == 3) ? Wl3 : Wa;
        for (int i = threadIdx.x; i < 8192; i += 256) {
            int n = i >> 6, k = i & 63;
            float wv;
            if (b < 4)
                wv = (n < 64) ? (W[k * 64 + n] - W[(k + 64) * 64 + n])
                              : W[(k + 64) * 64 + (n - 64)];
            else
                wv = W[k * 128 + n];
            __nv_bfloat16 hi = __float2bfloat16(wv);
            __nv_bfloat16 lo = __float2bfloat16(wv - __bfloat162float(hi));
            g_whi[b * 8192 + i] = hi;
            g_wlo[b * 8192 + i] = lo;
        }
        return;
    }
    __shared__ float sW[384];   // W1: 6 rows x 64
    __shared__ float sb[64];
    int tid = threadIdx.x;
    for (int i = tid; i < 448; i += 256) {
        if (i < 384) sW[i] = W1[i];
        else         sb[i - 384] = b1[i - 384];
    }
    __syncthreads();
    int lane = tid & 31;
    int node = blockIdx.x * 8 + (tid >> 5);
    float xv = (lane < 3) ? x[node * 3 + lane] : 0.f;
    float x0 = __shfl_sync(0xffffffffu, xv, 0);
    float x1 = __shfl_sync(0xffffffffu, xv, 1);
    float x2 = __shfl_sync(0xffffffffu, xv, 2);
    int c = lane * 2;
    float w30 = sW[192 + c], w31 = sW[193 + c];
    float w40 = sW[256 + c], w41 = sW[257 + c];
    float w50 = sW[320 + c], w51 = sW[321 + c];
    float q0 = x0 * w30 + x1 * w40 + x2 * w50;
    float q1 = x0 * w31 + x1 * w41 + x2 * w51;
    float p0 = sb[c]     + x0 * (sW[c] - w30)     + x1 * (sW[64 + c] - w40)
                         + x2 * (sW[128 + c] - w50);
    float p1 = sb[c + 1] + x0 * (sW[c + 1] - w31) + x1 * (sW[65 + c] - w41)
                         + x2 * (sW[129 + c] - w51);
    *(float2*)(g_pq + node * 128 + c)      = make_float2(p0, p1);
    *(float2*)(g_pq + node * 128 + 64 + c) = make_float2(q0, q1);
}

// ---------------- edge max: 2 nodes per warp, float4 lanes ------------------
__global__ void edge_kernel(int dogmax) {
    __shared__ unsigned sm[64];
    int gw   = (blockIdx.x * blockDim.x + threadIdx.x) >> 5;  // warp: 2 nodes
    int lane = threadIdx.x & 31;
    int half = lane >> 4;
    int hl   = lane & 15;
    int node = gw * 2 + half;
    int s = g_src[gw * 32 + lane];   // lanes 0-15: node0 srcs, 16-31: node1
    float4 m = make_float4(-3.402823466e38f, -3.402823466e38f,
                           -3.402823466e38f, -3.402823466e38f);
    const float* pq = g_pq;
#pragma unroll
    for (int k = 0; k < 16; k++) {
        int j = __shfl_sync(0xffffffffu, s, (half << 4) + k);
        float4 v = *(const float4*)(pq + j * 128 + 64 + hl * 4);
        m.x = fmaxf(m.x, v.x);
        m.y = fmaxf(m.y, v.y);
        m.z = fmaxf(m.z, v.z);
        m.w = fmaxf(m.w, v.w);
    }
    float4 p = *(const float4*)(pq + node * 128 + hl * 4);
    float r0 = fmaxf(p.x + m.x, 0.f);
    float r1 = fmaxf(p.y + m.y, 0.f);
    float r2 = fmaxf(p.z + m.z, 0.f);
    float r3 = fmaxf(p.w + m.w, 0.f);
    __nv_bfloat16 h0 = __float2bfloat16(r0), h1 = __float2bfloat16(r1);
    __nv_bfloat16 h2 = __float2bfloat16(r2), h3 = __float2bfloat16(r3);
    __nv_bfloat16 l0 = __float2bfloat16(r0 - __bfloat162float(h0));
    __nv_bfloat16 l1 = __float2bfloat16(r1 - __bfloat162float(h1));
    __nv_bfloat16 l2 = __float2bfloat16(r2 - __bfloat162float(h2));
    __nv_bfloat16 l3 = __float2bfloat16(r3 - __bfloat162float(h3));
    __nv_bfloat162 hp0 = __halves2bfloat162(h0, h1);
    __nv_bfloat162 hp1 = __halves2bfloat162(h2, h3);
    __nv_bfloat162 lp0 = __halves2bfloat162(l0, l1);
    __nv_bfloat162 lp1 = __halves2bfloat162(l2, l3);
    uint2 hv = make_uint2(*(u32*)&hp0, *(u32*)&hp1);
    uint2 lv = make_uint2(*(u32*)&lp0, *(u32*)&lp1);
    *(uint2*)(g_hhi + node * 64 + hl * 4) = hv;
    *(uint2*)(g_hlo + node * 64 + hl * 4) = lv;
    if (dogmax) {
        if (threadIdx.x < 64) sm[threadIdx.x] = 0u;
        __syncthreads();
        atomicMax(&sm[hl * 4 + 0], __float_as_uint(r0));   // r >= 0
        atomicMax(&sm[hl * 4 + 1], __float_as_uint(r1));
        atomicMax(&sm[hl * 4 + 2], __float_as_uint(r2));
        atomicMax(&sm[hl * 4 + 3], __float_as_uint(r3));
        __syncthreads();
        if (threadIdx.x < 64) atomicMax(&g_gmax[threadIdx.x], sm[threadIdx.x]);
    }
}

// ---------------- mma / ldmatrix / cp.async helpers -------------------------
static __device__ __forceinline__ void mma16816(float d[4], const u32 a[4],
                                                const u32 b[2]) {
    asm volatile(
        "mma.sync.aligned.m16n8k16.row.col.f32.bf16.bf16.f32 "
        "{%0,%1,%2,%3}, {%4,%5,%6,%7}, {%8,%9}, {%0,%1,%2,%3};"
        : "+f"(d[0]), "+f"(d[1]), "+f"(d[2]), "+f"(d[3])
        : "r"(a[0]), "r"(a[1]), "r"(a[2]), "r"(a[3]), "r"(b[0]), "r"(b[1]));
}
static __device__ __forceinline__ void ldsm4(u32 r[4], u32 addr) {
    asm volatile("ldmatrix.sync.aligned.m8n8.x4.shared.b16 {%0,%1,%2,%3}, [%4];"
        : "=r"(r[0]), "=r"(r[1]), "=r"(r[2]), "=r"(r[3]) : "r"(addr));
}
static __device__ __forceinline__ u32 smem_u32(const void* p) {
    u32 a;
    asm("{ .reg .u64 t; cvta.to.shared.u64 t, %1; cvt.u32.u64 %0, t; }"
        : "=r"(a) : "l"(p));
    return a;
}
static __device__ __forceinline__ void cpasync16(u32 dst, const void* src) {
    asm volatile("cp.async.cg.shared.global [%0], [%1], 16;"
        :: "r"(dst), "l"(src) : "memory");
}
static __device__ __forceinline__ void cpasync_wait_all() {
    asm volatile("cp.async.commit_group;\n\tcp.async.wait_group 0;" ::: "memory");
}

// ---------------- tensor-core GEMM: h[N,64] @ Wc[64,128] -> g_pq ------------
// CTA = 128M x 128N (grid 782, the best-measured shape), 8 warps.
// Warp tile 32M x 64N, M-OUTER loop (mt=0,1 of 16M x 64N) -> ~75 live regs,
// __launch_bounds__(256,3) => 3 CTAs/SM (smem 74.2KB, 222KB total).
// KEY CHANGE vs R7-R10: pass-separated mma order. Per kk, issue all 8 nf
// with Ahi, then all 8 with Alo, then all 8 with Blo -> same-accumulator
// reuse distance 8 mma (was 1), so HMMA latency no longer serializes issue.
// smem: Bhi[128][72]@0, Blo@18432, Ahi[128][72]@36864, Alo@55296,
//       bias@73728. Total 74240 B.
// mode 0: bias on cols 0-63.  mode 1: bias g_c128, relu at store.
__global__ void __launch_bounds__(256, 3) tc_gemm_kernel(int layer,
                                                         const float* __restrict__ bias,
                                                         int mode) {
    extern __shared__ unsigned char smem[];
    float* sB = (float*)(smem + 73728);
    int tid = threadIdx.x;
    int nb  = blockIdx.x * 128;
    u32 sbase = smem_u32(smem);

    // B: 128 rows x 8 chunks x {hi,lo} = 2048 chunks
    {
        const char* wh = (const char*)(g_whi + layer * 8192);
        const char* wl = (const char*)(g_wlo + layer * 8192);
#pragma unroll
        for (int c = tid; c < 2048; c += 256) {
            int half = c >> 10, idx = c & 1023;
            u32 off = (u32)(idx >> 3) * 144 + (u32)(idx & 7) * 16;
            cpasync16(sbase + half * 18432 + off,
                      (half ? wl : wh) + idx * 16);
        }
    }
    // A: 128 rows x 8 chunks x {hi,lo} = 2048 chunks (gmem oversized past NN)
    {
        const char* ah = (const char*)(g_hhi + (size_t)nb * 64);
        const char* al = (const char*)(g_hlo + (size_t)nb * 64);
#pragma unroll
        for (int c = tid; c < 2048; c += 256) {
            int half = c >> 10, idx = c & 1023;
            u32 off = (u32)(idx >> 3) * 144 + (u32)(idx & 7) * 16;
            cpasync16(sbase + 36864 + half * 18432 + off,
                      (half ? al : ah) + idx * 16);
        }
    }
    if (tid < 128)
        sB[tid] = (mode == 0) ? ((tid < 64) ? bias[tid] : 0.f) : g_c128[tid];
    cpasync_wait_all();
    __syncthreads();

    int lane = tid & 31;
    int wid  = tid >> 5;
    int wm   = wid & 3;      // rows wm*32..+32
    int wn   = wid >> 2;     // cols wn*64..+64

    int brow = wn * 64 + (lane & 7) + ((lane >> 4) << 3);
    u32 bHi = sbase + (brow * 72 + ((lane >> 3) & 1) * 8) * 2;
    u32 bLo = bHi + 18432;
    int r = lane >> 2, q = lane & 3;

#pragma unroll
    for (int mt = 0; mt < 2; mt++) {
        u32 aHi = sbase + 36864 +
                  ((wm * 32 + mt * 16 + (lane & 15)) * 72 + (lane >> 4) * 8) * 2;
        u32 aLo = aHi + 18432;

        float d[8][4];
#pragma unroll
        for (int nf = 0; nf < 8; nf++)
#pragma unroll
            for (int j = 0; j < 4; j++) d[nf][j] = 0.f;

#pragma unroll
        for (int kk = 0; kk < 4; kk++) {
            int ko = kk * 32;
            u32 ah[4], al[4], bb[4][4];
            ldsm4(ah, aHi + ko);
            ldsm4(al, aLo + ko);
#pragma unroll
            for (int p = 0; p < 4; p++) ldsm4(bb[p], bHi + p * 2304 + ko);
            // pass 1: Ahi * Bhi (8 independent accumulators)
#pragma unroll
            for (int nf = 0; nf < 8; nf++)
                mma16816(d[nf], ah, &bb[nf >> 1][(nf & 1) * 2]);
            // pass 2: Alo * Bhi
#pragma unroll
            for (int nf = 0; nf < 8; nf++)
                mma16816(d[nf], al, &bb[nf >> 1][(nf & 1) * 2]);
#pragma unroll
            for (int p = 0; p < 4; p++) ldsm4(bb[p], bLo + p * 2304 + ko);
            // pass 3: Ahi * Blo
#pragma unroll
            for (int nf = 0; nf < 8; nf++)
                mma16816(d[nf], ah, &bb[nf >> 1][(nf & 1) * 2]);
        }

        // epilogue for this mt
        int row0 = nb + wm * 32 + mt * 16 + r;
#pragma unroll
        for (int nf = 0; nf < 8; nf++) {
            int gcol = wn * 64 + nf * 8 + 2 * q;
            float bx = sB[gcol], by = sB[gcol + 1];
            float2 v0 = make_float2(d[nf][0] + bx, d[nf][1] + by);
            float2 v1 = make_float2(d[nf][2] + bx, d[nf][3] + by);
            if (mode == 1) {
                v0.x = fmaxf(v0.x, 0.f); v0.y = fmaxf(v0.y, 0.f);
                v1.x = fmaxf(v1.x, 0.f); v1.y = fmaxf(v1.y, 0.f);
            }
            if (row0 < NN)     *(float2*)(g_pq + row0 * 128 + gcol)       = v0;
            if (row0 + 8 < NN) *(float2*)(g_pq + (row0 + 8) * 128 + gcol) = v1;
        }
    }
}

// ---------------- c128 = ba + g @ Wa[64:128] --------------------------------
__global__ void c128_kernel(const float* __restrict__ Wa,
                            const float* __restrict__ ba) {
    int t = threadIdx.x;  // 128 threads
    float s = ba[t];
#pragma unroll 8
    for (int c = 0; c < 64; c++)
        s += __uint_as_float(g_gmax[c]) * Wa[(64 + c) * 128 + t];
    g_c128[t] = s;
}

// ---------------- head stage 2: out = x + r @ Wb + bb ----------------------
// ONE NODE PER WARP -> grid must cover NN warps = (NN*32)/256 blocks.
__global__ void head2_kernel(const float* __restrict__ Wb,
                             const float* __restrict__ bb,
                             const float* __restrict__ x,
                             float* __restrict__ out) {
    __shared__ float sWb[384];
    for (int i = threadIdx.x; i < 384; i += 256) sWb[i] = Wb[i];
    __syncthreads();
    int w    = (blockIdx.x * blockDim.x + threadIdx.x) >> 5;
    int lane = threadIdx.x & 31;
    if (w >= NN) return;
    float4 r4 = ((const float4*)(g_pq + w * 128))[lane];
    int t = lane * 4;
    float a0 = r4.x * sWb[t * 3 + 0] + r4.y * sWb[t * 3 + 3] +
               r4.z * sWb[t * 3 + 6] + r4.w * sWb[t * 3 + 9];
    float a1 = r4.x * sWb[t * 3 + 1] + r4.y * sWb[t * 3 + 4] +
               r4.z * sWb[t * 3 + 7] + r4.w * sWb[t * 3 + 10];
    float a2 = r4.x * sWb[t * 3 + 2] + r4.y * sWb[t * 3 + 5] +
               r4.z * sWb[t * 3 + 8] + r4.w * sWb[t * 3 + 11];
#pragma unroll
    for (int off = 16; off > 0; off >>= 1) {
        a0 += __shfl_down_sync(0xffffffffu, a0, off);
        a1 += __shfl_down_sync(0xffffffffu, a1, off);
        a2 += __shfl_down_sync(0xffffffffu, a2, off);
    }
    if (lane == 0) {
        out[w * 3 + 0] = x[w * 3 + 0] + bb[0] + a0;
        out[w * 3 + 1] = x[w * 3 + 1] + bb[1] + a1;
        out[w * 3 + 2] = x[w * 3 + 2] + bb[2] + a2;
    }
}

// ---------------- launch ----------------------------------------------------
extern "C" void kernel_launch(void* const* d_in, const int* in_sizes, int n_in,
                              void* d_out, int out_size) {
    (void)in_sizes; (void)n_in; (void)out_size;
    const float* x  = (const float*)d_in[0];
    const int*   ei = (const int*)d_in[1];
    const float* W1 = (const float*)d_in[2];
    const float* b1 = (const float*)d_in[3];
    const float* Wl[4] = {(const float*)d_in[4], (const float*)d_in[6],
                          (const float*)d_in[8], (const float*)d_in[10]};
    const float* bl[4] = {(const float*)d_in[5], (const float*)d_in[7],
                          (const float*)d_in[9], (const float*)d_in[11]};
    const float* Wa = (const float*)d_in[12];
    const float* ba = (const float*)d_in[13];
    const float* Wb = (const float*)d_in[14];
    const float* bb = (const float*)d_in[15];
    float* out = (float*)d_out;

    const int GEMM_SMEM = 74240;
    static bool attr_set = false;
    if (!attr_set) {
        cudaFuncSetAttribute(tc_gemm_kernel,
                             cudaFuncAttributeMaxDynamicSharedMemorySize,
                             GEMM_SMEM);
        attr_set = true;
    }

    convert_kernel<<<(EE + 255) / 256, 256>>>(ei);                        // #1
    layer1_kernel<<<12505, 256>>>(x, W1, b1, Wl[0], Wl[1], Wl[2], Wl[3], Wa); // #2
    edge_kernel<<<(NN * 16) / 256, 256>>>(0);                             // #3

    for (int l = 0; l < 4; l++) {
        tc_gemm_kernel<<<NT128, 256, GEMM_SMEM>>>(l, bl[l], 0);           // #4 (l=0)
        edge_kernel<<<(NN * 16) / 256, 256>>>(l == 3 ? 1 : 0);
    }

    c128_kernel<<<1, 128>>>(Wa, ba);
    tc_gemm_kernel<<<NT128, 256, GEMM_SMEM>>>(4, ba, 1);
    head2_kernel<<<(NN * 32) / 256, 256>>>(Wb, bb, x, out);   // 1 node/warp
}

// round 12
// speedup vs baseline: 1.1285x; 1.0727x over previous
#include <cuda_runtime.h>
#include <cuda_bf16.h>
#include <cstdint>

#define NN 100000
#define EE 1600000
#define NT128 ((NN + 127) / 128)   // 782 tiles of 128 rows

typedef uint32_t u32;

// ---------------- scratch (static device globals; no allocations) ----------
__device__ __nv_bfloat16  g_hhi[(NN + 128) * 64];  // node features, bf16 hi part
__device__ __nv_bfloat16  g_hlo[(NN + 128) * 64];  // node features, bf16 lo part
__device__ float          g_pq[NN * 128];  // p (cols 0-63), q (cols 64-127)
__device__ int            g_src[EE];       // int32 source indices
__device__ unsigned       g_gmax[64];      // global max bits (values >= 0)
__device__ float          g_c128[128];     // head constant: g @ Wa[64:128] + ba
__device__ __nv_bfloat16  g_whi[5 * 128 * 64];  // weight hi parts, [n][k] flat
__device__ __nv_bfloat16  g_wlo[5 * 128 * 64];  // weight lo parts

// ---------------- convert (fused gmax zero + dtype detect) ------------------
__global__ void convert_kernel(const int* __restrict__ ei) {
    __shared__ int s64;
    if (blockIdx.x == 0 && threadIdx.x < 64) g_gmax[threadIdx.x] = 0u;
    if (threadIdx.x == 0) {
        // int64 layout => odd words of src row all zero (0<=src<1e5);
        // int32 layout => P(all 64 zero) ~ 1e-320.
        int z = 0;
        for (int i = 0; i < 64; i++) z += (ei[2 * i + 1] == 0) ? 1 : 0;
        s64 = (z == 64) ? 1 : 0;
    }
    __syncthreads();
    int e = blockIdx.x * blockDim.x + threadIdx.x;
    if (e < EE) g_src[e] = s64 ? ei[2 * e] : ei[e];
}

// ---------------- layer 1: warp-per-node + fused weight prep ---------------
__global__ void layer1_kernel(const float* __restrict__ x,
                              const float* __restrict__ W1,
                              const float* __restrict__ b1,
                              const float* __restrict__ Wl0,
                              const float* __restrict__ Wl1,
                              const float* __restrict__ Wl2,
                              const float* __restrict__ Wl3,
                              const float* __restrict__ Wa) {
    if (blockIdx.x >= 12500) {
        int b = blockIdx.x - 12500;
        const float* W = (b == 0) ? Wl0 : (b == 1) ? Wl1 : (b == 2) ? Wl2
                       : (b == 3) ? Wl3 : Wa;
        for (int i = threadIdx.x; i < 8192; i += 256) {
            int n = i >> 6, k = i & 63;
            float wv;
            if (b < 4)
                wv = (n < 64) ? (W[k * 64 + n] - W[(k + 64) * 64 + n])
                              : W[(k + 64) * 64 + (n - 64)];
            else
                wv = W[k * 128 + n];
            __nv_bfloat16 hi = __float2bfloat16(wv);
            __nv_bfloat16 lo = __float2bfloat16(wv - __bfloat162float(hi));
            g_whi[b * 8192 + i] = hi;
            g_wlo[b * 8192 + i] = lo;
        }
        return;
    }
    __shared__ float sW[384];   // W1: 6 rows x 64
    __shared__ float sb[64];
    int tid = threadIdx.x;
    for (int i = tid; i < 448; i += 256) {
        if (i < 384) sW[i] = W1[i];
        else         sb[i - 384] = b1[i - 384];
    }
    __syncthreads();
    int lane = tid & 31;
    int node = blockIdx.x * 8 + (tid >> 5);
    float xv = (lane < 3) ? x[node * 3 + lane] : 0.f;
    float x0 = __shfl_sync(0xffffffffu, xv, 0);
    float x1 = __shfl_sync(0xffffffffu, xv, 1);
    float x2 = __shfl_sync(0xffffffffu, xv, 2);
    int c = lane * 2;
    float w30 = sW[192 + c], w31 = sW[193 + c];
    float w40 = sW[256 + c], w41 = sW[257 + c];
    float w50 = sW[320 + c], w51 = sW[321 + c];
    float q0 = x0 * w30 + x1 * w40 + x2 * w50;
    float q1 = x0 * w31 + x1 * w41 + x2 * w51;
    float p0 = sb[c]     + x0 * (sW[c] - w30)     + x1 * (sW[64 + c] - w40)
                         + x2 * (sW[128 + c] - w50);
    float p1 = sb[c + 1] + x0 * (sW[c + 1] - w31) + x1 * (sW[65 + c] - w41)
                         + x2 * (sW[129 + c] - w51);
    *(float2*)(g_pq + node * 128 + c)      = make_float2(p0, p1);
    *(float2*)(g_pq + node * 128 + 64 + c) = make_float2(q0, q1);
}

// ---------------- edge max: 2 nodes per warp, float4 lanes ------------------
__global__ void edge_kernel(int dogmax) {
    __shared__ unsigned sm[64];
    int gw   = (blockIdx.x * blockDim.x + threadIdx.x) >> 5;  // warp: 2 nodes
    int lane = threadIdx.x & 31;
    int half = lane >> 4;
    int hl   = lane & 15;
    int node = gw * 2 + half;
    int s = g_src[gw * 32 + lane];   // lanes 0-15: node0 srcs, 16-31: node1
    float4 m = make_float4(-3.402823466e38f, -3.402823466e38f,
                           -3.402823466e38f, -3.402823466e38f);
    const float* pq = g_pq;
#pragma unroll
    for (int k = 0; k < 16; k++) {
        int j = __shfl_sync(0xffffffffu, s, (half << 4) + k);
        float4 v = *(const float4*)(pq + j * 128 + 64 + hl * 4);
        m.x = fmaxf(m.x, v.x);
        m.y = fmaxf(m.y, v.y);
        m.z = fmaxf(m.z, v.z);
        m.w = fmaxf(m.w, v.w);
    }
    float4 p = *(const float4*)(pq + node * 128 + hl * 4);
    float r0 = fmaxf(p.x + m.x, 0.f);
    float r1 = fmaxf(p.y + m.y, 0.f);
    float r2 = fmaxf(p.z + m.z, 0.f);
    float r3 = fmaxf(p.w + m.w, 0.f);
    __nv_bfloat16 h0 = __float2bfloat16(r0), h1 = __float2bfloat16(r1);
    __nv_bfloat16 h2 = __float2bfloat16(r2), h3 = __float2bfloat16(r3);
    __nv_bfloat16 l0 = __float2bfloat16(r0 - __bfloat162float(h0));
    __nv_bfloat16 l1 = __float2bfloat16(r1 - __bfloat162float(h1));
    __nv_bfloat16 l2 = __float2bfloat16(r2 - __bfloat162float(h2));
    __nv_bfloat16 l3 = __float2bfloat16(r3 - __bfloat162float(h3));
    __nv_bfloat162 hp0 = __halves2bfloat162(h0, h1);
    __nv_bfloat162 hp1 = __halves2bfloat162(h2, h3);
    __nv_bfloat162 lp0 = __halves2bfloat162(l0, l1);
    __nv_bfloat162 lp1 = __halves2bfloat162(l2, l3);
    uint2 hv = make_uint2(*(u32*)&hp0, *(u32*)&hp1);
    uint2 lv = make_uint2(*(u32*)&lp0, *(u32*)&lp1);
    *(uint2*)(g_hhi + node * 64 + hl * 4) = hv;
    *(uint2*)(g_hlo + node * 64 + hl * 4) = lv;
    if (dogmax) {
        if (threadIdx.x < 64) sm[threadIdx.x] = 0u;
        __syncthreads();
        atomicMax(&sm[hl * 4 + 0], __float_as_uint(r0));   // r >= 0
        atomicMax(&sm[hl * 4 + 1], __float_as_uint(r1));
        atomicMax(&sm[hl * 4 + 2], __float_as_uint(r2));
        atomicMax(&sm[hl * 4 + 3], __float_as_uint(r3));
        __syncthreads();
        if (threadIdx.x < 64) atomicMax(&g_gmax[threadIdx.x], sm[threadIdx.x]);
    }
}

// ---------------- mma / ldmatrix / cp.async helpers -------------------------
static __device__ __forceinline__ void mma16816(float d[4], const u32 a[4],
                                                const u32 b[2]) {
    asm volatile(
        "mma.sync.aligned.m16n8k16.row.col.f32.bf16.bf16.f32 "
        "{%0,%1,%2,%3}, {%4,%5,%6,%7}, {%8,%9}, {%0,%1,%2,%3};"
        : "+f"(d[0]), "+f"(d[1]), "+f"(d[2]), "+f"(d[3])
        : "r"(a[0]), "r"(a[1]), "r"(a[2]), "r"(a[3]), "r"(b[0]), "r"(b[1]));
}
static __device__ __forceinline__ void ldsm4(u32 r[4], u32 addr) {
    asm volatile("ldmatrix.sync.aligned.m8n8.x4.shared.b16 {%0,%1,%2,%3}, [%4];"
        : "=r"(r[0]), "=r"(r[1]), "=r"(r[2]), "=r"(r[3]) : "r"(addr));
}
static __device__ __forceinline__ u32 smem_u32(const void* p) {
    u32 a;
    asm("{ .reg .u64 t; cvta.to.shared.u64 t, %1; cvt.u32.u64 %0, t; }"
        : "=r"(a) : "l"(p));
    return a;
}
static __device__ __forceinline__ void cpasync16(u32 dst, const void* src) {
    asm volatile("cp.async.cg.shared.global [%0], [%1], 16;"
        :: "r"(dst), "l"(src) : "memory");
}
static __device__ __forceinline__ void cpasync_wait_all() {
    asm volatile("cp.async.commit_group;\n\tcp.async.wait_group 0;" ::: "memory");
}

// ---------------- tensor-core GEMM: h[N,64] @ Wc[64,128] --------------------
// CTA = 128M x 128N (grid 782), 8 warps, warp tile 32M x 64N, M-OUTER loop.
// 3-pass bf16 hi/lo split, pass-separated mma order, fp32 accum.
// smem: Bhi[128][72]@0, Blo@18432, Ahi[128][72]@36864, Alo@55296,
//       bias@73728 (512B), Wb@74240 (1536B). Total 75776 B, 3 CTAs/SM.
// mode 0: writes p|q to g_pq; bias on cols 0-63.
// mode 1 (FUSED HEAD): bias g_c128, relu, then out += relu(feat) @ Wb
//   via quad-shfl reduction + global atomicAdd (out pre-init to x + bb).
//   No g_pq store, no separate head kernel.
__global__ void __launch_bounds__(256, 3) tc_gemm_kernel(int layer,
                                                         const float* __restrict__ bias,
                                                         int mode,
                                                         const float* __restrict__ Wb,
                                                         float* __restrict__ out) {
    extern __shared__ unsigned char smem[];
    float* sB  = (float*)(smem + 73728);
    float* sWb = (float*)(smem + 74240);
    int tid = threadIdx.x;
    int nb  = blockIdx.x * 128;
    u32 sbase = smem_u32(smem);

    // B: 128 rows x 8 chunks x {hi,lo} = 2048 chunks
    {
        const char* wh = (const char*)(g_whi + layer * 8192);
        const char* wl = (const char*)(g_wlo + layer * 8192);
#pragma unroll
        for (int c = tid; c < 2048; c += 256) {
            int half = c >> 10, idx = c & 1023;
            u32 off = (u32)(idx >> 3) * 144 + (u32)(idx & 7) * 16;
            cpasync16(sbase + half * 18432 + off,
                      (half ? wl : wh) + idx * 16);
        }
    }
    // A: 128 rows x 8 chunks x {hi,lo} = 2048 chunks (gmem oversized past NN)
    {
        const char* ah = (const char*)(g_hhi + (size_t)nb * 64);
        const char* al = (const char*)(g_hlo + (size_t)nb * 64);
#pragma unroll
        for (int c = tid; c < 2048; c += 256) {
            int half = c >> 10, idx = c & 1023;
            u32 off = (u32)(idx >> 3) * 144 + (u32)(idx & 7) * 16;
            cpasync16(sbase + 36864 + half * 18432 + off,
                      (half ? al : ah) + idx * 16);
        }
    }
    if (tid < 128)
        sB[tid] = (mode == 0) ? ((tid < 64) ? bias[tid] : 0.f) : g_c128[tid];
    if (mode == 1) {
        for (int i = tid; i < 384; i += 256) sWb[i] = Wb[i];
    }
    cpasync_wait_all();
    __syncthreads();

    int lane = tid & 31;
    int wid  = tid >> 5;
    int wm   = wid & 3;      // rows wm*32..+32
    int wn   = wid >> 2;     // cols wn*64..+64

    int brow = wn * 64 + (lane & 7) + ((lane >> 4) << 3);
    u32 bHi = sbase + (brow * 72 + ((lane >> 3) & 1) * 8) * 2;
    u32 bLo = bHi + 18432;
    int r = lane >> 2, q = lane & 3;

#pragma unroll
    for (int mt = 0; mt < 2; mt++) {
        u32 aHi = sbase + 36864 +
                  ((wm * 32 + mt * 16 + (lane & 15)) * 72 + (lane >> 4) * 8) * 2;
        u32 aLo = aHi + 18432;

        float d[8][4];
#pragma unroll
        for (int nf = 0; nf < 8; nf++)
#pragma unroll
            for (int j = 0; j < 4; j++) d[nf][j] = 0.f;

#pragma unroll
        for (int kk = 0; kk < 4; kk++) {
            int ko = kk * 32;
            u32 ah[4], al[4], bb[4][4];
            ldsm4(ah, aHi + ko);
            ldsm4(al, aLo + ko);
#pragma unroll
            for (int p = 0; p < 4; p++) ldsm4(bb[p], bHi + p * 2304 + ko);
#pragma unroll
            for (int nf = 0; nf < 8; nf++)
                mma16816(d[nf], ah, &bb[nf >> 1][(nf & 1) * 2]);
#pragma unroll
            for (int nf = 0; nf < 8; nf++)
                mma16816(d[nf], al, &bb[nf >> 1][(nf & 1) * 2]);
#pragma unroll
            for (int p = 0; p < 4; p++) ldsm4(bb[p], bLo + p * 2304 + ko);
#pragma unroll
            for (int nf = 0; nf < 8; nf++)
                mma16816(d[nf], ah, &bb[nf >> 1][(nf & 1) * 2]);
        }

        int row0 = nb + wm * 32 + mt * 16 + r;
        if (mode == 0) {
            // store p|q rows to g_pq
#pragma unroll
            for (int nf = 0; nf < 8; nf++) {
                int gcol = wn * 64 + nf * 8 + 2 * q;
                float bx = sB[gcol], by = sB[gcol + 1];
                float2 v0 = make_float2(d[nf][0] + bx, d[nf][1] + by);
                float2 v1 = make_float2(d[nf][2] + bx, d[nf][3] + by);
                if (row0 < NN)     *(float2*)(g_pq + row0 * 128 + gcol)       = v0;
                if (row0 + 8 < NN) *(float2*)(g_pq + (row0 + 8) * 128 + gcol) = v1;
            }
        } else {
            // fused head: out[row] += relu(feat) @ Wb
            float o0[3] = {0.f, 0.f, 0.f};
            float o1[3] = {0.f, 0.f, 0.f};
#pragma unroll
            for (int nf = 0; nf < 8; nf++) {
                int gcol = wn * 64 + nf * 8 + 2 * q;
                float bx = sB[gcol], by = sB[gcol + 1];
                float v00 = fmaxf(d[nf][0] + bx, 0.f);
                float v01 = fmaxf(d[nf][1] + by, 0.f);
                float v10 = fmaxf(d[nf][2] + bx, 0.f);
                float v11 = fmaxf(d[nf][3] + by, 0.f);
#pragma unroll
                for (int c = 0; c < 3; c++) {
                    float wb0 = sWb[gcol * 3 + c];
                    float wb1 = sWb[(gcol + 1) * 3 + c];
                    o0[c] += v00 * wb0 + v01 * wb1;
                    o1[c] += v10 * wb0 + v11 * wb1;
                }
            }
            // reduce over the 4 q-lanes (lanes r*4 + q)
#pragma unroll
            for (int msk = 1; msk <= 2; msk <<= 1) {
#pragma unroll
                for (int c = 0; c < 3; c++) {
                    o0[c] += __shfl_xor_sync(0xffffffffu, o0[c], msk);
                    o1[c] += __shfl_xor_sync(0xffffffffu, o1[c], msk);
                }
            }
            if (q == 0) {
#pragma unroll
                for (int c = 0; c < 3; c++) {
                    if (row0 < NN)     atomicAdd(out + row0 * 3 + c,       o0[c]);
                    if (row0 + 8 < NN) atomicAdd(out + (row0 + 8) * 3 + c, o1[c]);
                }
            }
        }
    }
}

// ---------------- c128 (block 0) + out init (blocks 1..) --------------------
// block 0: g_c128 = ba + g @ Wa[64:128].  blocks >= 1: out = x + bb.
__global__ void c128_kernel(const float* __restrict__ Wa,
                            const float* __restrict__ ba,
                            const float* __restrict__ bb,
                            const float* __restrict__ x,
                            float* __restrict__ out) {
    if (blockIdx.x == 0) {
        int t = threadIdx.x;
        if (t < 128) {
            float s = ba[t];
#pragma unroll 8
            for (int c = 0; c < 64; c++)
                s += __uint_as_float(g_gmax[c]) * Wa[(64 + c) * 128 + t];
            g_c128[t] = s;
        }
        return;
    }
    int idx = (blockIdx.x - 1) * 256 + threadIdx.x;
    if (idx < NN * 3) {
        int c = idx - (idx / 3) * 3;
        out[idx] = x[idx] + bb[c];
    }
}

// ---------------- launch ----------------------------------------------------
extern "C" void kernel_launch(void* const* d_in, const int* in_sizes, int n_in,
                              void* d_out, int out_size) {
    (void)in_sizes; (void)n_in; (void)out_size;
    const float* x  = (const float*)d_in[0];
    const int*   ei = (const int*)d_in[1];
    const float* W1 = (const float*)d_in[2];
    const float* b1 = (const float*)d_in[3];
    const float* Wl[4] = {(const float*)d_in[4], (const float*)d_in[6],
                          (const float*)d_in[8], (const float*)d_in[10]};
    const float* bl[4] = {(const float*)d_in[5], (const float*)d_in[7],
                          (const float*)d_in[9], (const float*)d_in[11]};
    const float* Wa = (const float*)d_in[12];
    const float* ba = (const float*)d_in[13];
    const float* Wb = (const float*)d_in[14];
    const float* bb = (const float*)d_in[15];
    float* out = (float*)d_out;

    const int GEMM_SMEM = 75776;
    static bool attr_set = false;
    if (!attr_set) {
        cudaFuncSetAttribute(tc_gemm_kernel,
                             cudaFuncAttributeMaxDynamicSharedMemorySize,
                             GEMM_SMEM);
        attr_set = true;
    }

    convert_kernel<<<(EE + 255) / 256, 256>>>(ei);                        // #1
    layer1_kernel<<<12505, 256>>>(x, W1, b1, Wl[0], Wl[1], Wl[2], Wl[3], Wa); // #2
    edge_kernel<<<(NN * 16) / 256, 256>>>(0);                             // #3

    for (int l = 0; l < 4; l++) {
        tc_gemm_kernel<<<NT128, 256, GEMM_SMEM>>>(l, bl[l], 0, nullptr, nullptr);
        edge_kernel<<<(NN * 16) / 256, 256>>>(l == 3 ? 1 : 0);
    }

    // c128 + out = x + bb init (must precede fused GEMM-5)
    c128_kernel<<<1 + (NN * 3 + 255) / 256, 256>>>(Wa, ba, bb, x, out);
    // GEMM-5 with fused head: out += relu(h@Wa[0:64] + c128) @ Wb
    tc_gemm_kernel<<<NT128, 256, GEMM_SMEM>>>(4, nullptr, 1, Wb, out);
}